// round 16
// baseline (speedup 1.0000x reference)
#include <cuda_runtime.h>
#include <cuda_bf16.h>
#include <cstdint>

// ---------------------------------------------------------------------------
// B=128, T=32, N=196, E=FD=H=A=1024, 4H=4096, E+FD=2048
// Gate-interleaved layout: gates column j' = 4*h + gate, gate in {i,f,g,o}
// ---------------------------------------------------------------------------

// ------------------------------ scratch ------------------------------------
__device__ __nv_bfloat16 g_fprojb[25088 * 1024];   // bf16 f_proj      51.4 MB
__device__ __nv_bfloat16 g_featsb[25088 * 1024];   // bf16 feats       51.4 MB
__device__ __nv_bfloat16 g_wfTb[1024 * 1024];      // bf16 Wf^T         2.1 MB
__device__ float g_embp[4096 * 1024];              // perm+tf32 emb    16.8 MB
__device__ float g_pre0[32 * 128 * 4096];          // fp32 interleaved 67.1 MB
__device__ float g_wqh[5120 * 1024];               // [Wh^T ; Whh0-int]21.0 MB
__device__ float g_w0a[4096 * 1024];               // Wih0 attn int    16.8 MB
__device__ float g_w0e[4096 * 1024];               // Wih0 embed int   16.8 MB
__device__ float g_w1c[4096 * 1024];               // (Wih1+Whh1) int  16.8 MB
__device__ float g_b0c[4096];                      // interleaved
__device__ float g_b1c[4096];                      // interleaved
__device__ float g_x[128 * 2048];                  // tf32 [attn | h0]
__device__ float g_c0[128 * 1024];
__device__ float g_q[128 * 1024];
__device__ float g_gpart[128 * 4096];              // h-half gates (interleaved)
__device__ float g_h0all[32 * 128 * 1024];         // tf32 [t][b][h]
__device__ float g_c0all[32 * 128 * 1024];
__device__ float g_gates1[32 * 128 * 4096];        // interleaved
__device__ unsigned g_barCnt[8];
__device__ unsigned g_barMid;
__device__ volatile unsigned g_barGen;

// ------------------------------ helpers ------------------------------------
__device__ __forceinline__ float fast_tanh(float x) {
    float r; asm("tanh.approx.f32 %0, %1;" : "=f"(r) : "f"(x)); return r;
}
__device__ __forceinline__ float sigf(float x) { return 1.f / (1.f + __expf(-x)); }
__device__ __forceinline__ float rnd_tf32(float x) {
    uint32_t r; asm("cvt.rna.tf32.f32 %0, %1;" : "=r"(r) : "f"(x));
    return __uint_as_float(r);
}
__device__ __forceinline__ void mma_tf32(float* c, const uint32_t* a, const uint32_t* b) {
    asm volatile(
        "mma.sync.aligned.m16n8k8.row.col.f32.tf32.tf32.f32 "
        "{%0,%1,%2,%3}, {%4,%5,%6,%7}, {%8,%9}, {%0,%1,%2,%3};"
        : "+f"(c[0]), "+f"(c[1]), "+f"(c[2]), "+f"(c[3])
        : "r"(a[0]), "r"(a[1]), "r"(a[2]), "r"(a[3]), "r"(b[0]), "r"(b[1]));
}
__device__ __forceinline__ void mma_bf16(float* c, const uint32_t* a, const uint32_t* b) {
    asm volatile(
        "mma.sync.aligned.m16n8k16.row.col.f32.bf16.bf16.f32 "
        "{%0,%1,%2,%3}, {%4,%5,%6,%7}, {%8,%9}, {%0,%1,%2,%3};"
        : "+f"(c[0]), "+f"(c[1]), "+f"(c[2]), "+f"(c[3])
        : "r"(a[0]), "r"(a[1]), "r"(a[2]), "r"(a[3]), "r"(b[0]), "r"(b[1]));
}
__device__ __forceinline__ uint32_t smem_u32(const void* p) {
    return (uint32_t)__cvta_generic_to_shared(p);
}
__device__ __forceinline__ void cp16(uint32_t dst, const void* src) {
    asm volatile("cp.async.cg.shared.global [%0], [%1], 16;" :: "r"(dst), "l"(src));
}
__device__ __forceinline__ unsigned long long mk_ef_policy() {
    unsigned long long p;
    asm("createpolicy.fractional.L2::evict_first.b64 %0, 1.0;" : "=l"(p));
    return p;
}
__device__ __forceinline__ unsigned long long mk_el_policy() {
    unsigned long long p;
    asm("createpolicy.fractional.L2::evict_last.b64 %0, 1.0;" : "=l"(p));
    return p;
}
__device__ __forceinline__ void cp16_ef(uint32_t dst, const void* src,
                                        unsigned long long pol) {
    asm volatile("cp.async.cg.shared.global.L2::cache_hint [%0], [%1], 16, %2;"
        :: "r"(dst), "l"(src), "l"(pol));
}
__device__ __forceinline__ uint4 ldg_el16(const void* p, unsigned long long pol) {
    uint4 r;
    asm("ld.global.nc.L2::cache_hint.v4.u32 {%0,%1,%2,%3}, [%4], %5;"
        : "=r"(r.x), "=r"(r.y), "=r"(r.z), "=r"(r.w) : "l"(p), "l"(pol));
    return r;
}
__device__ __forceinline__ uint32_t ldg_el4(const void* p, unsigned long long pol) {
    uint32_t r;
    asm("ld.global.nc.L2::cache_hint.u32 %0, [%1], %2;" : "=r"(r) : "l"(p), "l"(pol));
    return r;
}
__device__ __forceinline__ void ldsm4(uint32_t* r, uint32_t addr) {
    asm volatile("ldmatrix.sync.aligned.m8n8.x4.shared.b16 {%0,%1,%2,%3}, [%4];"
        : "=r"(r[0]), "=r"(r[1]), "=r"(r[2]), "=r"(r[3]) : "r"(addr));
}
__device__ __forceinline__ void team_barrier(int tm) {
    asm volatile("bar.sync %0, 256;" :: "r"(tm + 1) : "memory");
}

#define NBLK 148

// hierarchical barrier: 8 groups + master, hard spin (no nanosleep)
__device__ __forceinline__ void grid_sync() {
    __threadfence();
    __syncthreads();
    if (threadIdx.x == 0) {
        const unsigned gen = g_barGen;
        const int g = blockIdx.x & 7;
        const unsigned sz = (g < 4) ? 19u : 18u;
        if (atomicInc(&g_barCnt[g], sz - 1) == sz - 1) {
            if (atomicInc(&g_barMid, 7u) == 7u) {
                __threadfence();
                g_barGen = gen + 1;
            }
        }
        while (g_barGen == gen) { }
    }
    __syncthreads();
}

// ---------------------------------------------------------------------------
// Split-K team mainloop: team tm computes partial C[128,64] for k range
// [tm*512, tm*512+512), 16 serial iterations, 4-stage cp.async.
// ---------------------------------------------------------------------------
#define KITERS 16
#define CPITCH 68
#define STG_F  (128 * 36 + 64 * 36)
#define TEAM_F (4 * STG_F)

__device__ void team_mainloop(const float* __restrict__ A,       // lda 2048
                              const float* __restrict__ B,       // ldb 1024
                              float* tsm, int ttid, int tm, int n0,
                              unsigned long long pol)
{
    constexpr int KC = 32, PITCH = 36;
    constexpr int ASZ = 128 * PITCH;

    const int wid = ttid >> 5, lane = ttid & 31;
    const int wm = (wid & 3) * 32;
    const int wn = (wid >> 2) * 32;
    const int gg = lane >> 2, tg = lane & 3;
    const int lrow = ((lane >> 3) & 1) * 8 + (lane & 7);
    const int lcolA = (lane >> 4) * 4;
    const int browp = (lane >> 4) * 8 + (lane & 7);
    const int bcol = ((lane >> 3) & 1) * 4;
    const long kbase = (long)tm * 512;

    float acc[2][4][4];
#pragma unroll
    for (int f = 0; f < 2; f++)
#pragma unroll
        for (int j = 0; j < 4; j++)
#pragma unroll
            for (int k = 0; k < 4; k++) acc[f][j][k] = 0.f;

    auto issue = [&](int it) {
        const int s = it & 3;
        float* As = tsm + s * STG_F;
        float* Bs = As + ASZ;
        const long kb = kbase + (long)it * KC;
#pragma unroll
        for (int i = 0; i < 4; i++) {
            int c = ttid + i * 256;
            int row = c >> 3, kq = c & 7;
            cp16(smem_u32(As + row * PITCH + kq * 4),
                 A + (long)row * 2048 + kb + kq * 4);
        }
#pragma unroll
        for (int i = 0; i < 2; i++) {
            int c = ttid + i * 256;
            int row = c >> 3, kq = c & 7;
            cp16_ef(smem_u32(Bs + row * PITCH + kq * 4),
                    B + (long)(n0 + row) * 1024 + kb + kq * 4, pol);
        }
        asm volatile("cp.async.commit_group;" ::: "memory");
    };

    issue(0); issue(1); issue(2);
    for (int it = 0; it < KITERS; it++) {
        if (it < KITERS - 2)
            asm volatile("cp.async.wait_group 2;" ::: "memory");
        else if (it == KITERS - 2)
            asm volatile("cp.async.wait_group 1;" ::: "memory");
        else
            asm volatile("cp.async.wait_group 0;" ::: "memory");
        team_barrier(tm);
        if (it + 3 < KITERS) issue(it + 3);

        const float* As = tsm + (it & 3) * STG_F;
        const float* Bs = As + ASZ;
        const uint32_t aB = smem_u32(As), bB = smem_u32(Bs);

#pragma unroll
        for (int ko = 0; ko < KC; ko += 8) {
            uint32_t af[2][4];
#pragma unroll
            for (int f = 0; f < 2; f++)
                ldsm4(af[f], aB + ((wm + f * 16 + lrow) * PITCH + ko + lcolA) * 4);
            uint32_t bf[4][2];
#pragma unroll
            for (int nf = 0; nf < 4; nf += 2) {
                uint32_t tmp[4];
                ldsm4(tmp, bB + ((wn + nf * 8 + browp) * PITCH + ko + bcol) * 4);
                bf[nf][0] = tmp[0]; bf[nf][1] = tmp[1];
                bf[nf + 1][0] = tmp[2]; bf[nf + 1][1] = tmp[3];
            }
#pragma unroll
            for (int f = 0; f < 2; f++)
#pragma unroll
                for (int nf = 0; nf < 4; nf++)
                    mma_tf32(acc[f][nf], af[f], bf[nf]);
        }
    }

    team_barrier(tm);
#pragma unroll
    for (int f = 0; f < 2; f++) {
#pragma unroll
        for (int nf = 0; nf < 4; nf++) {
            const int col = wn + nf * 8 + tg * 2;
#pragma unroll
            for (int hh = 0; hh < 2; hh++) {
                const int row = wm + f * 16 + gg + hh * 8;
                tsm[row * CPITCH + col] = acc[f][nf][hh * 2 + 0];
                tsm[row * CPITCH + col + 1] = acc[f][nf][hh * 2 + 1];
            }
        }
    }
}

// ---------------------------------------------------------------------------
// attention body (512 threads, one block per b); energy 4 rows/warp for MLP
// ---------------------------------------------------------------------------
__device__ void attn_body(const float* __restrict__ v, int b, float* sm,
                          unsigned long long polL)
{
    const int tid = threadIdx.x;
    const int warp = tid >> 5, lane = tid & 31;
    float* qs = sm;
    float* sal = sm + 1024;
    float* red = sm + 1280;

    for (int a = tid; a < 1024; a += 512) qs[a] = __ldcg(&g_q[b * 1024 + a]);
    __syncthreads();

    // energy: 4 rows per warp per pass (rows base+warp+16j), 4 passes cover 256>=196
    for (int base = 0; base < 196; base += 64) {
        int nr[4];
        bool ok[4];
        const __nv_bfloat16* fp[4];
        float acc[4];
#pragma unroll
        for (int j = 0; j < 4; j++) {
            nr[j] = base + warp + j * 16;
            ok[j] = (nr[j] < 196);
            fp[j] = g_fprojb + (long)(b * 196 + (ok[j] ? nr[j] : 0)) * 1024;
            acc[j] = 0.f;
        }
#pragma unroll
        for (int i = 0; i < 4; i++) {
            const int k0 = i * 256 + lane * 8;
            uint4 raw[4];
#pragma unroll
            for (int j = 0; j < 4; j++) raw[j] = ldg_el16(fp[j] + k0, polL);
            float4 q0 = *(const float4*)(qs + k0);
            float4 q1 = *(const float4*)(qs + k0 + 4);
            float4 v0 = *(const float4*)(v + k0);
            float4 v1 = *(const float4*)(v + k0 + 4);
#pragma unroll
            for (int j = 0; j < 4; j++) {
                float2 f0 = __bfloat1622float2(*reinterpret_cast<__nv_bfloat162*>(&raw[j].x));
                float2 f1 = __bfloat1622float2(*reinterpret_cast<__nv_bfloat162*>(&raw[j].y));
                float2 f2 = __bfloat1622float2(*reinterpret_cast<__nv_bfloat162*>(&raw[j].z));
                float2 f3 = __bfloat1622float2(*reinterpret_cast<__nv_bfloat162*>(&raw[j].w));
                acc[j] = fmaf(v0.x, fast_tanh(f0.x + q0.x), acc[j]);
                acc[j] = fmaf(v0.y, fast_tanh(f0.y + q0.y), acc[j]);
                acc[j] = fmaf(v0.z, fast_tanh(f1.x + q0.z), acc[j]);
                acc[j] = fmaf(v0.w, fast_tanh(f1.y + q0.w), acc[j]);
                acc[j] = fmaf(v1.x, fast_tanh(f2.x + q1.x), acc[j]);
                acc[j] = fmaf(v1.y, fast_tanh(f2.y + q1.y), acc[j]);
                acc[j] = fmaf(v1.z, fast_tanh(f3.x + q1.z), acc[j]);
                acc[j] = fmaf(v1.w, fast_tanh(f3.y + q1.w), acc[j]);
            }
        }
#pragma unroll
        for (int j = 0; j < 4; j++) {
#pragma unroll
            for (int o = 16; o; o >>= 1)
                acc[j] += __shfl_xor_sync(0xffffffffu, acc[j], o);
            if (lane == 0 && ok[j]) sal[nr[j]] = acc[j];
        }
        if (base + 64 >= 196) break;
    }
    __syncthreads();

    float s = (tid < 196) ? sal[tid] : -3.0e38f;
    float m = s;
#pragma unroll
    for (int o = 16; o; o >>= 1) m = fmaxf(m, __shfl_xor_sync(0xffffffffu, m, o));
    if (lane == 0) red[warp] = m;
    __syncthreads();
    if (tid == 0) {
        float t2 = red[0];
        for (int i = 1; i < 16; i++) t2 = fmaxf(t2, red[i]);
        red[0] = t2;
    }
    __syncthreads();
    const float M = red[0];
    __syncthreads();

    float e = (tid < 196) ? __expf(s - M) : 0.f;
    float sm2 = e;
#pragma unroll
    for (int o = 16; o; o >>= 1) sm2 += __shfl_xor_sync(0xffffffffu, sm2, o);
    if (lane == 0) red[warp] = sm2;
    __syncthreads();
    if (tid == 0) {
        float t2 = 0.f;
        for (int i = 0; i < 16; i++) t2 += red[i];
        red[0] = t2;
    }
    __syncthreads();
    const float S = red[0];
    __syncthreads();
    if (tid < 196) sal[tid] = e / S;
    __syncthreads();

    const __nv_bfloat16* fb = g_featsb + (long)b * 196 * 1024;
    float a0 = 0.f, a1 = 0.f;
#pragma unroll 8
    for (int n = 0; n < 196; n++) {
        float al = sal[n];
        uint32_t pk = ldg_el4(fb + n * 1024 + tid * 2, polL);
        float2 f = __bfloat1622float2(*reinterpret_cast<__nv_bfloat162*>(&pk));
        a0 = fmaf(al, f.x, a0);
        a1 = fmaf(al, f.y, a1);
    }
    g_x[b * 2048 + tid * 2] = rnd_tf32(a0);
    g_x[b * 2048 + tid * 2 + 1] = rnd_tf32(a1);
}

// ---------------------------------------------------------------------------
// Persistent loop kernel: grid (NBLK,1,1), 512 threads.
// ---------------------------------------------------------------------------
__global__ __launch_bounds__(512, 1) void loop_kernel(const float* __restrict__ v)
{
    extern __shared__ float sm[];
    const int bid = blockIdx.x;
    const int tid = threadIdx.x;
    const int tm = tid >> 8;
    const int ttid = tid & 255;
    float* tsm0 = sm;
    float* tsm1 = sm + TEAM_F;
    float* tsm = sm + tm * TEAM_F;
    const unsigned long long polF = mk_ef_policy();
    const unsigned long long polL = mk_el_policy();

    for (int t = 0; t < 32; t++) {
        // ---- P1 ----
        if (bid < 80) {
            const int n0 = bid * 64;
            team_mainloop(g_x + 1024, g_wqh, tsm, ttid, tm, n0, polF);
            __syncthreads();
#pragma unroll
            for (int k = 0; k < 16; k++) {
                const int e = tid + k * 512;
                const int row = e >> 6, col = e & 63;
                float val = tsm0[row * CPITCH + col] + tsm1[row * CPITCH + col];
                const int gc = n0 + col;
                if (gc < 1024)
                    g_q[row * 1024 + gc] = val;
                else
                    g_gpart[row * 4096 + gc - 1024] = val;
            }
        }
        grid_sync();

        // ---- P2 ----
        if (bid < 128) attn_body(v, bid, sm, polL);
        grid_sync();

        // ---- P3 ----
        if (bid < 64) {
            const int n0 = bid * 64;
            const float* pre = g_pre0 + (size_t)t * 524288;
            team_mainloop(g_x, g_w0a, tsm, ttid, tm, n0, polF);
            __syncthreads();
#pragma unroll
            for (int u = 0; u < 4; u++) {
                const int idx = tid + u * 512;
                const int b = idx >> 4, hl = idx & 15;
                const int cl = hl * 4;
                float4 ga = *(const float4*)&tsm0[b * CPITCH + cl];
                float4 gb = *(const float4*)&tsm1[b * CPITCH + cl];
                float4 pr = __ldcs((const float4*)&pre[b * 4096 + n0 + cl]);
                float4 gp = *(const float4*)&g_gpart[b * 4096 + n0 + cl];
                float gi = ga.x + gb.x + pr.x + gp.x;
                float gf = ga.y + gb.y + pr.y + gp.y;
                float gG = ga.z + gb.z + pr.z + gp.z;
                float go = ga.w + gb.w + pr.w + gp.w;
                const int h = (n0 >> 2) + hl;
                float c = g_c0[b * 1024 + h];
                float cn = sigf(gf) * c + sigf(gi) * tanhf(gG);
                float hn = sigf(go) * tanhf(cn);
                float hr = rnd_tf32(hn);
                g_c0[b * 1024 + h] = cn;
                g_x[b * 2048 + 1024 + h] = hr;
                __stcs(&g_h0all[t * 131072 + b * 1024 + h], hr);
                __stcs(&g_c0all[t * 131072 + b * 1024 + h], cn);
            }
        }
        grid_sync();
    }
}

// ---------------------------------------------------------------------------
// big tf32 GEMM (BN=128, 2-stage) — pre0, gates1
// ---------------------------------------------------------------------------
template <bool BIAS>
__global__ __launch_bounds__(256) void mma_gemm_big(
    const float* __restrict__ A, int lda,
    const float* __restrict__ B, int ldb,
    float* __restrict__ Cf, int ldc,
    const float* __restrict__ bias, int K)
{
    constexpr int KC = 32, PITCH = 36;
    constexpr int ASZ = 128 * PITCH, BSZ = 128 * PITCH;

    extern __shared__ float sm[];
    const int tid = threadIdx.x;
    const int wid = tid >> 5, lane = tid & 31;
    const int m0 = blockIdx.x * 128;
    const int n0 = blockIdx.y * 128;
    const int wm = (wid & 3) * 32;
    const int wn = (wid >> 2) * 64;
    const int gg = lane >> 2, tg = lane & 3;
    const int NIT = K / KC;

    const int lrow = ((lane >> 3) & 1) * 8 + (lane & 7);
    const int lcolA = (lane >> 4) * 4;
    const int browp = (lane >> 4) * 8 + (lane & 7);
    const int bcol = ((lane >> 3) & 1) * 4;

    float acc[2][8][4];
#pragma unroll
    for (int f = 0; f < 2; f++)
#pragma unroll
        for (int j = 0; j < 8; j++)
#pragma unroll
            for (int k = 0; k < 4; k++) acc[f][j][k] = 0.f;

    auto issue = [&](int it) {
        const int s = it & 1;
        float* As = sm + s * (ASZ + BSZ);
        float* Bs = As + ASZ;
        const long kb = (long)it * KC;
#pragma unroll
        for (int i = 0; i < 4; i++) {
            int c = tid + i * 256;
            int row = c >> 3, kq = c & 7;
            cp16(smem_u32(As + row * PITCH + kq * 4),
                 A + (long)(m0 + row) * lda + kb + kq * 4);
        }
#pragma unroll
        for (int i = 0; i < 4; i++) {
            int c = tid + i * 256;
            int row = c >> 3, kq = c & 7;
            cp16(smem_u32(Bs + row * PITCH + kq * 4),
                 B + (long)(n0 + row) * ldb + kb + kq * 4);
        }
        asm volatile("cp.async.commit_group;" ::: "memory");
    };

    issue(0);
    for (int it = 0; it < NIT; it++) {
        asm volatile("cp.async.wait_group 0;" ::: "memory");
        __syncthreads();
        if (it + 1 < NIT) issue(it + 1);
        const float* As = sm + (it & 1) * (ASZ + BSZ);
        const float* Bs = As + ASZ;
        const uint32_t aB = smem_u32(As), bB = smem_u32(Bs);
#pragma unroll
        for (int ko = 0; ko < KC; ko += 8) {
            uint32_t af[2][4];
#pragma unroll
            for (int f = 0; f < 2; f++)
                ldsm4(af[f], aB + ((wm + f * 16 + lrow) * PITCH + ko + lcolA) * 4);
            uint32_t bf[8][2];
#pragma unroll
            for (int nf = 0; nf < 8; nf += 2) {
                uint32_t tmp[4];
                ldsm4(tmp, bB + ((wn + nf * 8 + browp) * PITCH + ko + bcol) * 4);
                bf[nf][0] = tmp[0]; bf[nf][1] = tmp[1];
                bf[nf + 1][0] = tmp[2]; bf[nf + 1][1] = tmp[3];
            }
#pragma unroll
            for (int f = 0; f < 2; f++)
#pragma unroll
                for (int nf = 0; nf < 8; nf++)
                    mma_tf32(acc[f][nf], af[f], bf[nf]);
        }
        __syncthreads();
    }

#pragma unroll
    for (int f = 0; f < 2; f++) {
#pragma unroll
        for (int nf = 0; nf < 8; nf++) {
            const int col = n0 + wn + nf * 8 + tg * 2;
#pragma unroll
            for (int hh = 0; hh < 2; hh++) {
                const long row = m0 + wm + f * 16 + gg + hh * 8;
                float v0 = acc[f][nf][hh * 2 + 0];
                float v1 = acc[f][nf][hh * 2 + 1];
                if (BIAS) { v0 += bias[col]; v1 += bias[col + 1]; }
                Cf[row * ldc + col] = v0;
                Cf[row * ldc + col + 1] = v1;
            }
        }
    }
}

// ---------------------------------------------------------------------------
// bf16 m16n8k16 GEMM for f_proj
// ---------------------------------------------------------------------------
__global__ __launch_bounds__(256) void mma_gemm_fproj(
    const __nv_bfloat16* __restrict__ A,
    const __nv_bfloat16* __restrict__ B,
    __nv_bfloat16* __restrict__ C,
    const float* __restrict__ bias)
{
    constexpr int KC = 32;
    constexpr int PITCH = 40;
    constexpr int ASZ = 128 * PITCH, BSZ = 128 * PITCH;
    constexpr int K = 1024, NIT = K / KC;

    extern __shared__ __nv_bfloat16 smh[];
    const int tid = threadIdx.x;
    const int wid = tid >> 5, lane = tid & 31;
    const int m0 = blockIdx.x * 128;
    const int n0 = blockIdx.y * 128;
    const int wm = (wid & 3) * 32;
    const int wn = (wid >> 2) * 64;
    const int gg = lane >> 2, tg = lane & 3;

    const int lrow = ((lane >> 3) & 1) * 8 + (lane & 7);
    const int lcol = (lane >> 4) * 8;

    float acc[2][8][4];
#pragma unroll
    for (int f = 0; f < 2; f++)
#pragma unroll
        for (int j = 0; j < 8; j++)
#pragma unroll
            for (int k = 0; k < 4; k++) acc[f][j][k] = 0.f;

    auto issue = [&](int it) {
        const int s = it & 1;
        __nv_bfloat16* As = smh + s * (ASZ + BSZ);
        __nv_bfloat16* Bs = As + ASZ;
        const long kb = (long)it * KC;
#pragma unroll
        for (int i = 0; i < 2; i++) {
            int c = tid + i * 256;
            int row = c >> 2, kq = c & 3;
            cp16(smem_u32(As + row * PITCH + kq * 8),
                 A + (long)(m0 + row) * 1024 + kb + kq * 8);
        }
#pragma unroll
        for (int i = 0; i < 2; i++) {
            int c = tid + i * 256;
            int row = c >> 2, kq = c & 3;
            cp16(smem_u32(Bs + row * PITCH + kq * 8),
                 B + (long)(n0 + row) * 1024 + kb + kq * 8);
        }
        asm volatile("cp.async.commit_group;" ::: "memory");
    };

    issue(0);
    for (int it = 0; it < NIT; it++) {
        asm volatile("cp.async.wait_group 0;" ::: "memory");
        __syncthreads();
        if (it + 1 < NIT) issue(it + 1);
        const __nv_bfloat16* As = smh + (it & 1) * (ASZ + BSZ);
        const __nv_bfloat16* Bs = As + ASZ;
        const uint32_t aB = smem_u32(As), bB = smem_u32(Bs);
#pragma unroll
        for (int ko = 0; ko < KC; ko += 16) {
            uint32_t af[2][4];
#pragma unroll
            for (int f = 0; f < 2; f++)
                ldsm4(af[f], aB + ((wm + f * 16 + lrow) * PITCH + ko + lcol) * 2);
            uint32_t bf[8][2];
#pragma unroll
            for (int nf = 0; nf < 8; nf += 2) {
                uint32_t tmp[4];
                const int br = wn + nf * 8 + (lane >> 4) * 8 + (lane & 7);
                const int bc = ko + ((lane >> 3) & 1) * 8;
                ldsm4(tmp, bB + (br * PITCH + bc) * 2);
                bf[nf][0] = tmp[0]; bf[nf][1] = tmp[1];
                bf[nf + 1][0] = tmp[2]; bf[nf + 1][1] = tmp[3];
            }
#pragma unroll
            for (int f = 0; f < 2; f++)
#pragma unroll
                for (int nf = 0; nf < 8; nf++)
                    mma_bf16(acc[f][nf], af[f], bf[nf]);
        }
        __syncthreads();
    }

#pragma unroll
    for (int f = 0; f < 2; f++) {
#pragma unroll
        for (int nf = 0; nf < 8; nf++) {
            const int col = n0 + wn + nf * 8 + tg * 2;
#pragma unroll
            for (int hh = 0; hh < 2; hh++) {
                const long row = m0 + wm + f * 16 + gg + hh * 8;
                float v0 = acc[f][nf][hh * 2 + 0] + bias[col];
                float v1 = acc[f][nf][hh * 2 + 1] + bias[col + 1];
                *(__nv_bfloat162*)&C[row * 1024 + col] =
                    __float22bfloat162_rn(make_float2(v0, v1));
            }
        }
    }
}

// ---------------------------------------------------------------------------
__global__ __launch_bounds__(256) void cell1_kernel(float* __restrict__ out)
{
    const int idx = blockIdx.x * 256 + threadIdx.x;
    const int m = idx >> 10, h = idx & 1023;
    const float4 gq = *(const float4*)&g_gates1[(long)m * 4096 + h * 4];
    float c0n = g_c0all[idx];
    float c1 = sigf(gq.y) * c0n + sigf(gq.x) * tanhf(gq.z);
    float h1 = sigf(gq.w) * tanhf(c1);
    const int b = m & 127, t = m >> 7;
    out[(long)(b * 32 + t) * 1024 + h] = h1;
}

// ---------------------------------------------------------------------------
__global__ __launch_bounds__(256) void prep_all(
    const float* __restrict__ feats,
    const float* __restrict__ emb,
    const float* __restrict__ Wf, const float* __restrict__ Wh,
    const float* __restrict__ W_ih0, const float* __restrict__ W_hh0,
    const float* __restrict__ W_ih1, const float* __restrict__ W_hh1,
    const float* __restrict__ b_ih0, const float* __restrict__ b_hh0,
    const float* __restrict__ b_ih1, const float* __restrict__ b_hh1)
{
    const int i = blockIdx.x * 256 + threadIdx.x;
    const int stride = gridDim.x * 256;

    for (int idx = i; idx < 4096 * 1024; idx += stride) {
        const int n = idx >> 10, k = idx & 1023;
        const int gidx = n >> 10, hh = n & 1023;
        const int rp = hh * 4 + gidx;
        g_wqh[(1024 + rp) * 1024 + k] = rnd_tf32(W_hh0[n * 1024 + k]);
        g_w0a[rp * 1024 + k] = rnd_tf32(W_ih0[n * 2048 + 1024 + k]);
        g_w0e[rp * 1024 + k] = rnd_tf32(W_ih0[n * 2048 + k]);
        g_w1c[rp * 1024 + k] = rnd_tf32(W_ih1[n * 1024 + k] + W_hh1[n * 1024 + k]);
        g_embp[idx] = rnd_tf32(emb[((n & 127) * 32 + (n >> 7)) * 1024 + k]);
    }
    for (int idx = i; idx < 1024 * 1024; idx += stride) {
        const int a = idx >> 10, c = idx & 1023;
        g_wqh[a * 1024 + c] = rnd_tf32(Wh[c * 1024 + a]);
        g_wfTb[a * 1024 + c] = __float2bfloat16_rn(Wf[c * 1024 + a]);
    }
    for (long idx = i; idx < 25088L * 1024 / 4; idx += stride) {
        const long e = idx * 4;
        float4 f = *(const float4*)(feats + e);
        *(__nv_bfloat162*)&g_featsb[e] = __float22bfloat162_rn(make_float2(f.x, f.y));
        *(__nv_bfloat162*)&g_featsb[e + 2] = __float22bfloat162_rn(make_float2(f.z, f.w));
    }
    for (int idx = i; idx < 128 * 2048; idx += stride) g_x[idx] = 0.f;
    for (int idx = i; idx < 128 * 1024; idx += stride) g_c0[idx] = 0.f;
    if (i < 4096) {
        const int gidx = i >> 10, hh = i & 1023;
        const int rp = hh * 4 + gidx;
        g_b0c[rp] = b_ih0[i] + b_hh0[i];
        g_b1c[rp] = b_ih1[i] + b_hh1[i];
    }
}

// ---------------------------------------------------------------------------
extern "C" void kernel_launch(void* const* d_in, const int* in_sizes, int n_in,
                              void* d_out, int out_size)
{
    const float* feats = (const float*)d_in[0];
    const float* emb   = (const float*)d_in[1];
    const float* Wf    = (const float*)d_in[2];
    const float* Wh    = (const float*)d_in[3];
    const float* b_att = (const float*)d_in[4];
    const float* v     = (const float*)d_in[5];
    const float* W_ih0 = (const float*)d_in[6];
    const float* W_hh0 = (const float*)d_in[7];
    const float* b_ih0 = (const float*)d_in[8];
    const float* b_hh0 = (const float*)d_in[9];
    const float* W_ih1 = (const float*)d_in[10];
    const float* W_hh1 = (const float*)d_in[11];
    const float* b_ih1 = (const float*)d_in[12];
    const float* b_hh1 = (const float*)d_in[13];
    float* out = (float*)d_out;

    void *p_fprojb, *p_featsb, *p_wfTb, *p_embp, *p_pre0, *p_w0e, *p_w1c;
    void *p_b0c, *p_b1c, *p_h0all, *p_gates1;
    cudaGetSymbolAddress(&p_fprojb, g_fprojb);
    cudaGetSymbolAddress(&p_featsb, g_featsb);
    cudaGetSymbolAddress(&p_wfTb, g_wfTb);
    cudaGetSymbolAddress(&p_embp, g_embp);
    cudaGetSymbolAddress(&p_pre0, g_pre0);
    cudaGetSymbolAddress(&p_w0e, g_w0e);
    cudaGetSymbolAddress(&p_w1c, g_w1c);
    cudaGetSymbolAddress(&p_b0c, g_b0c);
    cudaGetSymbolAddress(&p_b1c, g_b1c);
    cudaGetSymbolAddress(&p_h0all, g_h0all);
    cudaGetSymbolAddress(&p_gates1, g_gates1);

    constexpr int SMEM_BIG = 2 * (128 * 36 + 128 * 36) * 4;   // 73728
    constexpr int SMEM_BF = 2 * (128 * 40 + 128 * 40) * 2;    // 40960
    constexpr int SMEM_LOOP = 2 * TEAM_F * 4;                 // 221184
    cudaFuncSetAttribute(mma_gemm_big<true>,
                         cudaFuncAttributeMaxDynamicSharedMemorySize, SMEM_BIG);
    cudaFuncSetAttribute(loop_kernel,
                         cudaFuncAttributeMaxDynamicSharedMemorySize, SMEM_LOOP);

    prep_all<<<2048, 256>>>(feats, emb, Wf, Wh, W_ih0, W_hh0, W_ih1, W_hh1,
                            b_ih0, b_hh0, b_ih1, b_hh1);

    mma_gemm_fproj<<<dim3(196, 8), 256, SMEM_BF>>>(
        (const __nv_bfloat16*)p_featsb, (const __nv_bfloat16*)p_wfTb,
        (__nv_bfloat16*)p_fprojb, b_att);

    mma_gemm_big<true><<<dim3(32, 32), 256, SMEM_BIG>>>(
        (const float*)p_embp, 1024, (const float*)p_w0e, 1024,
        (float*)p_pre0, 4096, (const float*)p_b0c, 1024);

    loop_kernel<<<NBLK, 512, SMEM_LOOP>>>(v);

    mma_gemm_big<true><<<dim3(32, 32), 256, SMEM_BIG>>>(
        (const float*)p_h0all, 1024, (const float*)p_w1c, 1024,
        (float*)p_gates1, 4096, (const float*)p_b1c, 1024);

    cell1_kernel<<<16384, 256>>>(out);
}

// round 17
// speedup vs baseline: 1.0551x; 1.0551x over previous
#include <cuda_runtime.h>
#include <cuda_bf16.h>
#include <cstdint>

// ---------------------------------------------------------------------------
// B=128, T=32, N=196, E=FD=H=A=1024, 4H=4096, E+FD=2048
// Gate-interleaved layout: gates column j' = 4*h + gate, gate in {i,f,g,o}
// pre0 slice computed per-step inside P1 (idle blocks 84..147).
// ---------------------------------------------------------------------------

// ------------------------------ scratch ------------------------------------
__device__ __nv_bfloat16 g_fprojb[25088 * 1024];   // bf16 f_proj      51.4 MB
__device__ __nv_bfloat16 g_featsb[25088 * 1024];   // bf16 feats       51.4 MB
__device__ __nv_bfloat16 g_wfTb[1024 * 1024];      // bf16 Wf^T         2.1 MB
__device__ float g_embp[4096 * 1024];              // tf32 emb (natural)16.8 MB
__device__ float g_pre[128 * 4096];                // per-step pre0     2.1 MB
__device__ float g_wqh[5120 * 1024];               // [Wh^T ; Whh0-int]21.0 MB
__device__ float g_w0a[4096 * 1024];               // Wih0 attn int    16.8 MB
__device__ float g_w0e[4096 * 1024];               // Wih0 embed int   16.8 MB
__device__ float g_w1c[4096 * 1024];               // (Wih1+Whh1) int  16.8 MB
__device__ float g_b0c[4096];                      // interleaved
__device__ float g_b1c[4096];                      // interleaved
__device__ float g_x[128 * 2048];                  // tf32 [attn | h0]
__device__ float g_c0[128 * 1024];
__device__ float g_q[128 * 1024];
__device__ float g_gpart[128 * 4096];              // h-half gates (interleaved)
__device__ float g_h0all[32 * 128 * 1024];         // tf32 [t][b][h]
__device__ float g_c0all[32 * 128 * 1024];
__device__ float g_gates1[32 * 128 * 4096];        // interleaved
__device__ unsigned g_barCnt[8];
__device__ unsigned g_barMid;
__device__ volatile unsigned g_barGen;

// ------------------------------ helpers ------------------------------------
__device__ __forceinline__ float fast_tanh(float x) {
    float r; asm("tanh.approx.f32 %0, %1;" : "=f"(r) : "f"(x)); return r;
}
__device__ __forceinline__ float sigf(float x) { return 1.f / (1.f + __expf(-x)); }
__device__ __forceinline__ float rnd_tf32(float x) {
    uint32_t r; asm("cvt.rna.tf32.f32 %0, %1;" : "=r"(r) : "f"(x));
    return __uint_as_float(r);
}
__device__ __forceinline__ void mma_tf32(float* c, const uint32_t* a, const uint32_t* b) {
    asm volatile(
        "mma.sync.aligned.m16n8k8.row.col.f32.tf32.tf32.f32 "
        "{%0,%1,%2,%3}, {%4,%5,%6,%7}, {%8,%9}, {%0,%1,%2,%3};"
        : "+f"(c[0]), "+f"(c[1]), "+f"(c[2]), "+f"(c[3])
        : "r"(a[0]), "r"(a[1]), "r"(a[2]), "r"(a[3]), "r"(b[0]), "r"(b[1]));
}
__device__ __forceinline__ void mma_bf16(float* c, const uint32_t* a, const uint32_t* b) {
    asm volatile(
        "mma.sync.aligned.m16n8k16.row.col.f32.bf16.bf16.f32 "
        "{%0,%1,%2,%3}, {%4,%5,%6,%7}, {%8,%9}, {%0,%1,%2,%3};"
        : "+f"(c[0]), "+f"(c[1]), "+f"(c[2]), "+f"(c[3])
        : "r"(a[0]), "r"(a[1]), "r"(a[2]), "r"(a[3]), "r"(b[0]), "r"(b[1]));
}
__device__ __forceinline__ uint32_t smem_u32(const void* p) {
    return (uint32_t)__cvta_generic_to_shared(p);
}
__device__ __forceinline__ void cp16(uint32_t dst, const void* src) {
    asm volatile("cp.async.cg.shared.global [%0], [%1], 16;" :: "r"(dst), "l"(src));
}
__device__ __forceinline__ unsigned long long mk_ef_policy() {
    unsigned long long p;
    asm("createpolicy.fractional.L2::evict_first.b64 %0, 1.0;" : "=l"(p));
    return p;
}
__device__ __forceinline__ unsigned long long mk_el_policy() {
    unsigned long long p;
    asm("createpolicy.fractional.L2::evict_last.b64 %0, 1.0;" : "=l"(p));
    return p;
}
__device__ __forceinline__ void cp16_ef(uint32_t dst, const void* src,
                                        unsigned long long pol) {
    asm volatile("cp.async.cg.shared.global.L2::cache_hint [%0], [%1], 16, %2;"
        :: "r"(dst), "l"(src), "l"(pol));
}
__device__ __forceinline__ uint4 ldg_el16(const void* p, unsigned long long pol) {
    uint4 r;
    asm("ld.global.nc.L2::cache_hint.v4.u32 {%0,%1,%2,%3}, [%4], %5;"
        : "=r"(r.x), "=r"(r.y), "=r"(r.z), "=r"(r.w) : "l"(p), "l"(pol));
    return r;
}
__device__ __forceinline__ uint32_t ldg_el4(const void* p, unsigned long long pol) {
    uint32_t r;
    asm("ld.global.nc.L2::cache_hint.u32 %0, [%1], %2;" : "=r"(r) : "l"(p), "l"(pol));
    return r;
}
__device__ __forceinline__ void ldsm4(uint32_t* r, uint32_t addr) {
    asm volatile("ldmatrix.sync.aligned.m8n8.x4.shared.b16 {%0,%1,%2,%3}, [%4];"
        : "=r"(r[0]), "=r"(r[1]), "=r"(r[2]), "=r"(r[3]) : "r"(addr));
}
__device__ __forceinline__ void team_barrier(int tm) {
    asm volatile("bar.sync %0, 256;" :: "r"(tm + 1) : "memory");
}

#define NBLK 148

// hierarchical barrier: 8 groups + master
__device__ __forceinline__ void grid_sync() {
    __threadfence();
    __syncthreads();
    if (threadIdx.x == 0) {
        const unsigned gen = g_barGen;
        const int g = blockIdx.x & 7;
        const unsigned sz = (g < 4) ? 19u : 18u;
        if (atomicInc(&g_barCnt[g], sz - 1) == sz - 1) {
            if (atomicInc(&g_barMid, 7u) == 7u) {
                __threadfence();
                g_barGen = gen + 1;
            }
        }
        while (g_barGen == gen) { __nanosleep(20); }
    }
    __syncthreads();
}

// ---------------------------------------------------------------------------
// Split-K team mainloop: team tm computes partial C[128,64] for k range
// [tm*512, tm*512+512), 16 serial iterations, 4-stage cp.async.
// ---------------------------------------------------------------------------
#define KITERS 16
#define CPITCH 68
#define STG_F  (128 * 36 + 64 * 36)
#define TEAM_F (4 * STG_F)

__device__ void team_mainloop(const float* __restrict__ A, long lda,
                              const float* __restrict__ B,       // ldb 1024
                              float* tsm, int ttid, int tm, int n0,
                              unsigned long long pol)
{
    constexpr int KC = 32, PITCH = 36;
    constexpr int ASZ = 128 * PITCH;

    const int wid = ttid >> 5, lane = ttid & 31;
    const int wm = (wid & 3) * 32;
    const int wn = (wid >> 2) * 32;
    const int gg = lane >> 2, tg = lane & 3;
    const int lrow = ((lane >> 3) & 1) * 8 + (lane & 7);
    const int lcolA = (lane >> 4) * 4;
    const int browp = (lane >> 4) * 8 + (lane & 7);
    const int bcol = ((lane >> 3) & 1) * 4;
    const long kbase = (long)tm * 512;

    float acc[2][4][4];
#pragma unroll
    for (int f = 0; f < 2; f++)
#pragma unroll
        for (int j = 0; j < 4; j++)
#pragma unroll
            for (int k = 0; k < 4; k++) acc[f][j][k] = 0.f;

    auto issue = [&](int it) {
        const int s = it & 3;
        float* As = tsm + s * STG_F;
        float* Bs = As + ASZ;
        const long kb = kbase + (long)it * KC;
#pragma unroll
        for (int i = 0; i < 4; i++) {
            int c = ttid + i * 256;
            int row = c >> 3, kq = c & 7;
            cp16(smem_u32(As + row * PITCH + kq * 4),
                 A + (long)row * lda + kb + kq * 4);
        }
#pragma unroll
        for (int i = 0; i < 2; i++) {
            int c = ttid + i * 256;
            int row = c >> 3, kq = c & 7;
            cp16_ef(smem_u32(Bs + row * PITCH + kq * 4),
                    B + (long)(n0 + row) * 1024 + kb + kq * 4, pol);
        }
        asm volatile("cp.async.commit_group;" ::: "memory");
    };

    issue(0); issue(1); issue(2);
    for (int it = 0; it < KITERS; it++) {
        if (it < KITERS - 2)
            asm volatile("cp.async.wait_group 2;" ::: "memory");
        else if (it == KITERS - 2)
            asm volatile("cp.async.wait_group 1;" ::: "memory");
        else
            asm volatile("cp.async.wait_group 0;" ::: "memory");
        team_barrier(tm);
        if (it + 3 < KITERS) issue(it + 3);

        const float* As = tsm + (it & 3) * STG_F;
        const float* Bs = As + ASZ;
        const uint32_t aB = smem_u32(As), bB = smem_u32(Bs);

#pragma unroll
        for (int ko = 0; ko < KC; ko += 8) {
            uint32_t af[2][4];
#pragma unroll
            for (int f = 0; f < 2; f++)
                ldsm4(af[f], aB + ((wm + f * 16 + lrow) * PITCH + ko + lcolA) * 4);
            uint32_t bf[4][2];
#pragma unroll
            for (int nf = 0; nf < 4; nf += 2) {
                uint32_t tmp[4];
                ldsm4(tmp, bB + ((wn + nf * 8 + browp) * PITCH + ko + bcol) * 4);
                bf[nf][0] = tmp[0]; bf[nf][1] = tmp[1];
                bf[nf + 1][0] = tmp[2]; bf[nf + 1][1] = tmp[3];
            }
#pragma unroll
            for (int f = 0; f < 2; f++)
#pragma unroll
                for (int nf = 0; nf < 4; nf++)
                    mma_tf32(acc[f][nf], af[f], bf[nf]);
        }
    }

    team_barrier(tm);
#pragma unroll
    for (int f = 0; f < 2; f++) {
#pragma unroll
        for (int nf = 0; nf < 4; nf++) {
            const int col = wn + nf * 8 + tg * 2;
#pragma unroll
            for (int hh = 0; hh < 2; hh++) {
                const int row = wm + f * 16 + gg + hh * 8;
                tsm[row * CPITCH + col] = acc[f][nf][hh * 2 + 0];
                tsm[row * CPITCH + col + 1] = acc[f][nf][hh * 2 + 1];
            }
        }
    }
}

// ---------------------------------------------------------------------------
// attention body (512 threads, one block per b); energy 2 rows/warp
// ---------------------------------------------------------------------------
__device__ void attn_body(const float* __restrict__ v, int b, float* sm,
                          unsigned long long polL)
{
    const int tid = threadIdx.x;
    const int warp = tid >> 5, lane = tid & 31;
    float* qs = sm;
    float* sal = sm + 1024;
    float* red = sm + 1280;

    for (int a = tid; a < 1024; a += 512) qs[a] = __ldcg(&g_q[b * 1024 + a]);
    __syncthreads();

    for (int nb = warp; nb < 196; nb += 32) {
        const int n2 = nb + 16;
        const bool has2 = (n2 < 196);
        const __nv_bfloat16* fp0 = g_fprojb + (long)(b * 196 + nb) * 1024;
        const __nv_bfloat16* fp1 = has2 ? g_fprojb + (long)(b * 196 + n2) * 1024 : fp0;
        float acc0 = 0.f, acc1 = 0.f;
#pragma unroll
        for (int i = 0; i < 4; i++) {
            const int k0 = i * 256 + lane * 8;
            uint4 ra = ldg_el16(fp0 + k0, polL);
            uint4 rb = ldg_el16(fp1 + k0, polL);
            float4 q0 = *(const float4*)(qs + k0);
            float4 q1 = *(const float4*)(qs + k0 + 4);
            float4 v0 = *(const float4*)(v + k0);
            float4 v1 = *(const float4*)(v + k0 + 4);
            {
                float2 f0 = __bfloat1622float2(*reinterpret_cast<__nv_bfloat162*>(&ra.x));
                float2 f1 = __bfloat1622float2(*reinterpret_cast<__nv_bfloat162*>(&ra.y));
                float2 f2 = __bfloat1622float2(*reinterpret_cast<__nv_bfloat162*>(&ra.z));
                float2 f3 = __bfloat1622float2(*reinterpret_cast<__nv_bfloat162*>(&ra.w));
                acc0 = fmaf(v0.x, fast_tanh(f0.x + q0.x), acc0);
                acc0 = fmaf(v0.y, fast_tanh(f0.y + q0.y), acc0);
                acc0 = fmaf(v0.z, fast_tanh(f1.x + q0.z), acc0);
                acc0 = fmaf(v0.w, fast_tanh(f1.y + q0.w), acc0);
                acc0 = fmaf(v1.x, fast_tanh(f2.x + q1.x), acc0);
                acc0 = fmaf(v1.y, fast_tanh(f2.y + q1.y), acc0);
                acc0 = fmaf(v1.z, fast_tanh(f3.x + q1.z), acc0);
                acc0 = fmaf(v1.w, fast_tanh(f3.y + q1.w), acc0);
            }
            {
                float2 f0 = __bfloat1622float2(*reinterpret_cast<__nv_bfloat162*>(&rb.x));
                float2 f1 = __bfloat1622float2(*reinterpret_cast<__nv_bfloat162*>(&rb.y));
                float2 f2 = __bfloat1622float2(*reinterpret_cast<__nv_bfloat162*>(&rb.z));
                float2 f3 = __bfloat1622float2(*reinterpret_cast<__nv_bfloat162*>(&rb.w));
                acc1 = fmaf(v0.x, fast_tanh(f0.x + q0.x), acc1);
                acc1 = fmaf(v0.y, fast_tanh(f0.y + q0.y), acc1);
                acc1 = fmaf(v0.z, fast_tanh(f1.x + q0.z), acc1);
                acc1 = fmaf(v0.w, fast_tanh(f1.y + q0.w), acc1);
                acc1 = fmaf(v1.x, fast_tanh(f2.x + q1.x), acc1);
                acc1 = fmaf(v1.y, fast_tanh(f2.y + q1.y), acc1);
                acc1 = fmaf(v1.z, fast_tanh(f3.x + q1.z), acc1);
                acc1 = fmaf(v1.w, fast_tanh(f3.y + q1.w), acc1);
            }
        }
#pragma unroll
        for (int o = 16; o; o >>= 1) {
            acc0 += __shfl_xor_sync(0xffffffffu, acc0, o);
            acc1 += __shfl_xor_sync(0xffffffffu, acc1, o);
        }
        if (lane == 0) {
            sal[nb] = acc0;
            if (has2) sal[n2] = acc1;
        }
    }
    __syncthreads();

    float s = (tid < 196) ? sal[tid] : -3.0e38f;
    float m = s;
#pragma unroll
    for (int o = 16; o; o >>= 1) m = fmaxf(m, __shfl_xor_sync(0xffffffffu, m, o));
    if (lane == 0) red[warp] = m;
    __syncthreads();
    if (tid == 0) {
        float t2 = red[0];
        for (int i = 1; i < 16; i++) t2 = fmaxf(t2, red[i]);
        red[0] = t2;
    }
    __syncthreads();
    const float M = red[0];
    __syncthreads();

    float e = (tid < 196) ? __expf(s - M) : 0.f;
    float sm2 = e;
#pragma unroll
    for (int o = 16; o; o >>= 1) sm2 += __shfl_xor_sync(0xffffffffu, sm2, o);
    if (lane == 0) red[warp] = sm2;
    __syncthreads();
    if (tid == 0) {
        float t2 = 0.f;
        for (int i = 0; i < 16; i++) t2 += red[i];
        red[0] = t2;
    }
    __syncthreads();
    const float S = red[0];
    __syncthreads();
    if (tid < 196) sal[tid] = e / S;
    __syncthreads();

    const __nv_bfloat16* fb = g_featsb + (long)b * 196 * 1024;
    float a0 = 0.f, a1 = 0.f;
#pragma unroll 8
    for (int n = 0; n < 196; n++) {
        float al = sal[n];
        uint32_t pk = ldg_el4(fb + n * 1024 + tid * 2, polL);
        float2 f = __bfloat1622float2(*reinterpret_cast<__nv_bfloat162*>(&pk));
        a0 = fmaf(al, f.x, a0);
        a1 = fmaf(al, f.y, a1);
    }
    g_x[b * 2048 + tid * 2] = rnd_tf32(a0);
    g_x[b * 2048 + tid * 2 + 1] = rnd_tf32(a1);
}

// ---------------------------------------------------------------------------
// Persistent loop kernel: grid (NBLK,1,1), 512 threads.
// P1: blocks 0..79 tiles of [q|gates_h]; blocks 84..147 pre0 slice tiles.
// P2: blocks 0..127 attention.
// P3: blocks 0..63 gates_a(+pre+gpart) + fused cell.
// ---------------------------------------------------------------------------
__global__ __launch_bounds__(512, 1) void loop_kernel(const float* __restrict__ v)
{
    extern __shared__ float sm[];
    const int bid = blockIdx.x;
    const int tid = threadIdx.x;
    const int tm = tid >> 8;
    const int ttid = tid & 255;
    float* tsm0 = sm;
    float* tsm1 = sm + TEAM_F;
    float* tsm = sm + tm * TEAM_F;
    const unsigned long long polF = mk_ef_policy();
    const unsigned long long polL = mk_el_policy();

    for (int t = 0; t < 32; t++) {
        // ---- P1 ----
        if (bid < 80) {
            const int n0 = bid * 64;
            team_mainloop(g_x + 1024, 2048, g_wqh, tsm, ttid, tm, n0, polF);
            __syncthreads();
#pragma unroll
            for (int k = 0; k < 16; k++) {
                const int e = tid + k * 512;
                const int row = e >> 6, col = e & 63;
                float val = tsm0[row * CPITCH + col] + tsm1[row * CPITCH + col];
                const int gc = n0 + col;
                if (gc < 1024)
                    g_q[row * 1024 + gc] = val;
                else
                    g_gpart[row * 4096 + gc - 1024] = val;
            }
        } else if (bid >= 84) {
            // pre0 slice: pre[b][n0+col] = emb[b][t] @ w0e^T + b0c
            const int n0 = (bid - 84) * 64;
            team_mainloop(g_embp + (long)t * 1024, 32768, g_w0e,
                          tsm, ttid, tm, n0, polF);
            __syncthreads();
#pragma unroll
            for (int k = 0; k < 16; k++) {
                const int e = tid + k * 512;
                const int row = e >> 6, col = e & 63;
                float val = tsm0[row * CPITCH + col] + tsm1[row * CPITCH + col]
                          + g_b0c[n0 + col];
                g_pre[row * 4096 + n0 + col] = val;
            }
        }
        grid_sync();

        // ---- P2 ----
        if (bid < 128) attn_body(v, bid, sm, polL);
        grid_sync();

        // ---- P3 ----
        if (bid < 64) {
            const int n0 = bid * 64;
            team_mainloop(g_x, 2048, g_w0a, tsm, ttid, tm, n0, polF);
            __syncthreads();
#pragma unroll
            for (int u = 0; u < 4; u++) {
                const int idx = tid + u * 512;
                const int b = idx >> 4, hl = idx & 15;
                const int cl = hl * 4;
                float4 ga = *(const float4*)&tsm0[b * CPITCH + cl];
                float4 gb = *(const float4*)&tsm1[b * CPITCH + cl];
                float4 pr = *(const float4*)&g_pre[b * 4096 + n0 + cl];
                float4 gp = *(const float4*)&g_gpart[b * 4096 + n0 + cl];
                float gi = ga.x + gb.x + pr.x + gp.x;
                float gf = ga.y + gb.y + pr.y + gp.y;
                float gG = ga.z + gb.z + pr.z + gp.z;
                float go = ga.w + gb.w + pr.w + gp.w;
                const int h = (n0 >> 2) + hl;
                float c = g_c0[b * 1024 + h];
                float cn = sigf(gf) * c + sigf(gi) * tanhf(gG);
                float hn = sigf(go) * tanhf(cn);
                float hr = rnd_tf32(hn);
                g_c0[b * 1024 + h] = cn;
                g_x[b * 2048 + 1024 + h] = hr;
                __stcs(&g_h0all[t * 131072 + b * 1024 + h], hr);
                __stcs(&g_c0all[t * 131072 + b * 1024 + h], cn);
            }
        }
        grid_sync();
    }
}

// ---------------------------------------------------------------------------
// big tf32 GEMM (BN=128, 2-stage) — gates1
// ---------------------------------------------------------------------------
__global__ __launch_bounds__(256) void mma_gemm_big(
    const float* __restrict__ A, int lda,
    const float* __restrict__ B, int ldb,
    float* __restrict__ Cf, int ldc,
    const float* __restrict__ bias, int K)
{
    constexpr int KC = 32, PITCH = 36;
    constexpr int ASZ = 128 * PITCH, BSZ = 128 * PITCH;

    extern __shared__ float sm[];
    const int tid = threadIdx.x;
    const int wid = tid >> 5, lane = tid & 31;
    const int m0 = blockIdx.x * 128;
    const int n0 = blockIdx.y * 128;
    const int wm = (wid & 3) * 32;
    const int wn = (wid >> 2) * 64;
    const int gg = lane >> 2, tg = lane & 3;
    const int NIT = K / KC;

    const int lrow = ((lane >> 3) & 1) * 8 + (lane & 7);
    const int lcolA = (lane >> 4) * 4;
    const int browp = (lane >> 4) * 8 + (lane & 7);
    const int bcol = ((lane >> 3) & 1) * 4;

    float acc[2][8][4];
#pragma unroll
    for (int f = 0; f < 2; f++)
#pragma unroll
        for (int j = 0; j < 8; j++)
#pragma unroll
            for (int k = 0; k < 4; k++) acc[f][j][k] = 0.f;

    auto issue = [&](int it) {
        const int s = it & 1;
        float* As = sm + s * (ASZ + BSZ);
        float* Bs = As + ASZ;
        const long kb = (long)it * KC;
#pragma unroll
        for (int i = 0; i < 4; i++) {
            int c = tid + i * 256;
            int row = c >> 3, kq = c & 7;
            cp16(smem_u32(As + row * PITCH + kq * 4),
                 A + (long)(m0 + row) * lda + kb + kq * 4);
        }
#pragma unroll
        for (int i = 0; i < 4; i++) {
            int c = tid + i * 256;
            int row = c >> 3, kq = c & 7;
            cp16(smem_u32(Bs + row * PITCH + kq * 4),
                 B + (long)(n0 + row) * ldb + kb + kq * 4);
        }
        asm volatile("cp.async.commit_group;" ::: "memory");
    };

    issue(0);
    for (int it = 0; it < NIT; it++) {
        asm volatile("cp.async.wait_group 0;" ::: "memory");
        __syncthreads();
        if (it + 1 < NIT) issue(it + 1);
        const float* As = sm + (it & 1) * (ASZ + BSZ);
        const float* Bs = As + ASZ;
        const uint32_t aB = smem_u32(As), bB = smem_u32(Bs);
#pragma unroll
        for (int ko = 0; ko < KC; ko += 8) {
            uint32_t af[2][4];
#pragma unroll
            for (int f = 0; f < 2; f++)
                ldsm4(af[f], aB + ((wm + f * 16 + lrow) * PITCH + ko + lcolA) * 4);
            uint32_t bf[8][2];
#pragma unroll
            for (int nf = 0; nf < 8; nf += 2) {
                uint32_t tmp[4];
                ldsm4(tmp, bB + ((wn + nf * 8 + browp) * PITCH + ko + bcol) * 4);
                bf[nf][0] = tmp[0]; bf[nf][1] = tmp[1];
                bf[nf + 1][0] = tmp[2]; bf[nf + 1][1] = tmp[3];
            }
#pragma unroll
            for (int f = 0; f < 2; f++)
#pragma unroll
                for (int nf = 0; nf < 8; nf++)
                    mma_tf32(acc[f][nf], af[f], bf[nf]);
        }
        __syncthreads();
    }

#pragma unroll
    for (int f = 0; f < 2; f++) {
#pragma unroll
        for (int nf = 0; nf < 8; nf++) {
            const int col = n0 + wn + nf * 8 + tg * 2;
#pragma unroll
            for (int hh = 0; hh < 2; hh++) {
                const long row = m0 + wm + f * 16 + gg + hh * 8;
                float v0 = acc[f][nf][hh * 2 + 0] + bias[col];
                float v1 = acc[f][nf][hh * 2 + 1] + bias[col + 1];
                Cf[row * ldc + col] = v0;
                Cf[row * ldc + col + 1] = v1;
            }
        }
    }
}

// ---------------------------------------------------------------------------
// bf16 m16n8k16 GEMM for f_proj
// ---------------------------------------------------------------------------
__global__ __launch_bounds__(256) void mma_gemm_fproj(
    const __nv_bfloat16* __restrict__ A,
    const __nv_bfloat16* __restrict__ B,
    __nv_bfloat16* __restrict__ C,
    const float* __restrict__ bias)
{
    constexpr int KC = 32;
    constexpr int PITCH = 40;
    constexpr int ASZ = 128 * PITCH, BSZ = 128 * PITCH;
    constexpr int K = 1024, NIT = K / KC;

    extern __shared__ __nv_bfloat16 smh[];
    const int tid = threadIdx.x;
    const int wid = tid >> 5, lane = tid & 31;
    const int m0 = blockIdx.x * 128;
    const int n0 = blockIdx.y * 128;
    const int wm = (wid & 3) * 32;
    const int wn = (wid >> 2) * 64;
    const int gg = lane >> 2, tg = lane & 3;

    const int lrow = ((lane >> 3) & 1) * 8 + (lane & 7);
    const int lcol = (lane >> 4) * 8;

    float acc[2][8][4];
#pragma unroll
    for (int f = 0; f < 2; f++)
#pragma unroll
        for (int j = 0; j < 8; j++)
#pragma unroll
            for (int k = 0; k < 4; k++) acc[f][j][k] = 0.f;

    auto issue = [&](int it) {
        const int s = it & 1;
        __nv_bfloat16* As = smh + s * (ASZ + BSZ);
        __nv_bfloat16* Bs = As + ASZ;
        const long kb = (long)it * KC;
#pragma unroll
        for (int i = 0; i < 2; i++) {
            int c = tid + i * 256;
            int row = c >> 2, kq = c & 3;
            cp16(smem_u32(As + row * PITCH + kq * 8),
                 A + (long)(m0 + row) * 1024 + kb + kq * 8);
        }
#pragma unroll
        for (int i = 0; i < 2; i++) {
            int c = tid + i * 256;
            int row = c >> 2, kq = c & 3;
            cp16(smem_u32(Bs + row * PITCH + kq * 8),
                 B + (long)(n0 + row) * 1024 + kb + kq * 8);
        }
        asm volatile("cp.async.commit_group;" ::: "memory");
    };

    issue(0);
    for (int it = 0; it < NIT; it++) {
        asm volatile("cp.async.wait_group 0;" ::: "memory");
        __syncthreads();
        if (it + 1 < NIT) issue(it + 1);
        const __nv_bfloat16* As = smh + (it & 1) * (ASZ + BSZ);
        const __nv_bfloat16* Bs = As + ASZ;
        const uint32_t aB = smem_u32(As), bB = smem_u32(Bs);
#pragma unroll
        for (int ko = 0; ko < KC; ko += 16) {
            uint32_t af[2][4];
#pragma unroll
            for (int f = 0; f < 2; f++)
                ldsm4(af[f], aB + ((wm + f * 16 + lrow) * PITCH + ko + lcol) * 2);
            uint32_t bf[8][2];
#pragma unroll
            for (int nf = 0; nf < 8; nf += 2) {
                uint32_t tmp[4];
                const int br = wn + nf * 8 + (lane >> 4) * 8 + (lane & 7);
                const int bc = ko + ((lane >> 3) & 1) * 8;
                ldsm4(tmp, bB + (br * PITCH + bc) * 2);
                bf[nf][0] = tmp[0]; bf[nf][1] = tmp[1];
                bf[nf + 1][0] = tmp[2]; bf[nf + 1][1] = tmp[3];
            }
#pragma unroll
            for (int f = 0; f < 2; f++)
#pragma unroll
                for (int nf = 0; nf < 8; nf++)
                    mma_bf16(acc[f][nf], af[f], bf[nf]);
        }
        __syncthreads();
    }

#pragma unroll
    for (int f = 0; f < 2; f++) {
#pragma unroll
        for (int nf = 0; nf < 8; nf++) {
            const int col = n0 + wn + nf * 8 + tg * 2;
#pragma unroll
            for (int hh = 0; hh < 2; hh++) {
                const long row = m0 + wm + f * 16 + gg + hh * 8;
                float v0 = acc[f][nf][hh * 2 + 0] + bias[col];
                float v1 = acc[f][nf][hh * 2 + 1] + bias[col + 1];
                *(__nv_bfloat162*)&C[row * 1024 + col] =
                    __float22bfloat162_rn(make_float2(v0, v1));
            }
        }
    }
}

// ---------------------------------------------------------------------------
__global__ __launch_bounds__(256) void cell1_kernel(float* __restrict__ out)
{
    const int idx = blockIdx.x * 256 + threadIdx.x;
    const int m = idx >> 10, h = idx & 1023;
    const float4 gq = *(const float4*)&g_gates1[(long)m * 4096 + h * 4];
    float c0n = g_c0all[idx];
    float c1 = sigf(gq.y) * c0n + sigf(gq.x) * tanhf(gq.z);
    float h1 = sigf(gq.w) * tanhf(c1);
    const int b = m & 127, t = m >> 7;
    out[(long)(b * 32 + t) * 1024 + h] = h1;
}

// ---------------------------------------------------------------------------
__global__ __launch_bounds__(256) void prep_all(
    const float* __restrict__ feats,
    const float* __restrict__ emb,
    const float* __restrict__ Wf, const float* __restrict__ Wh,
    const float* __restrict__ W_ih0, const float* __restrict__ W_hh0,
    const float* __restrict__ W_ih1, const float* __restrict__ W_hh1,
    const float* __restrict__ b_ih0, const float* __restrict__ b_hh0,
    const float* __restrict__ b_ih1, const float* __restrict__ b_hh1)
{
    const int i = blockIdx.x * 256 + threadIdx.x;
    const int stride = gridDim.x * 256;

    for (int idx = i; idx < 4096 * 1024; idx += stride) {
        const int n = idx >> 10, k = idx & 1023;
        const int gidx = n >> 10, hh = n & 1023;
        const int rp = hh * 4 + gidx;
        g_wqh[(1024 + rp) * 1024 + k] = rnd_tf32(W_hh0[n * 1024 + k]);
        g_w0a[rp * 1024 + k] = rnd_tf32(W_ih0[n * 2048 + 1024 + k]);
        g_w0e[rp * 1024 + k] = rnd_tf32(W_ih0[n * 2048 + k]);
        g_w1c[rp * 1024 + k] = rnd_tf32(W_ih1[n * 1024 + k] + W_hh1[n * 1024 + k]);
        g_embp[idx] = rnd_tf32(emb[idx]);       // natural [b][t][k] layout
    }
    for (int idx = i; idx < 1024 * 1024; idx += stride) {
        const int a = idx >> 10, c = idx & 1023;
        g_wqh[a * 1024 + c] = rnd_tf32(Wh[c * 1024 + a]);
        g_wfTb[a * 1024 + c] = __float2bfloat16_rn(Wf[c * 1024 + a]);
    }
    for (long idx = i; idx < 25088L * 1024 / 4; idx += stride) {
        const long e = idx * 4;
        float4 f = *(const float4*)(feats + e);
        *(__nv_bfloat162*)&g_featsb[e] = __float22bfloat162_rn(make_float2(f.x, f.y));
        *(__nv_bfloat162*)&g_featsb[e + 2] = __float22bfloat162_rn(make_float2(f.z, f.w));
    }
    for (int idx = i; idx < 128 * 2048; idx += stride) g_x[idx] = 0.f;
    for (int idx = i; idx < 128 * 1024; idx += stride) g_c0[idx] = 0.f;
    if (i < 4096) {
        const int gidx = i >> 10, hh = i & 1023;
        const int rp = hh * 4 + gidx;
        g_b0c[rp] = b_ih0[i] + b_hh0[i];
        g_b1c[rp] = b_ih1[i] + b_hh1[i];
    }
}

// ---------------------------------------------------------------------------
extern "C" void kernel_launch(void* const* d_in, const int* in_sizes, int n_in,
                              void* d_out, int out_size)
{
    const float* feats = (const float*)d_in[0];
    const float* emb   = (const float*)d_in[1];
    const float* Wf    = (const float*)d_in[2];
    const float* Wh    = (const float*)d_in[3];
    const float* b_att = (const float*)d_in[4];
    const float* v     = (const float*)d_in[5];
    const float* W_ih0 = (const float*)d_in[6];
    const float* W_hh0 = (const float*)d_in[7];
    const float* b_ih0 = (const float*)d_in[8];
    const float* b_hh0 = (const float*)d_in[9];
    const float* W_ih1 = (const float*)d_in[10];
    const float* W_hh1 = (const float*)d_in[11];
    const float* b_ih1 = (const float*)d_in[12];
    const float* b_hh1 = (const float*)d_in[13];
    float* out = (float*)d_out;

    void *p_fprojb, *p_featsb, *p_wfTb, *p_w1c, *p_b1c, *p_h0all, *p_gates1;
    cudaGetSymbolAddress(&p_fprojb, g_fprojb);
    cudaGetSymbolAddress(&p_featsb, g_featsb);
    cudaGetSymbolAddress(&p_wfTb, g_wfTb);
    cudaGetSymbolAddress(&p_w1c, g_w1c);
    cudaGetSymbolAddress(&p_b1c, g_b1c);
    cudaGetSymbolAddress(&p_h0all, g_h0all);
    cudaGetSymbolAddress(&p_gates1, g_gates1);

    constexpr int SMEM_BIG = 2 * (128 * 36 + 128 * 36) * 4;   // 73728
    constexpr int SMEM_BF = 2 * (128 * 40 + 128 * 40) * 2;    // 40960
    constexpr int SMEM_LOOP = 2 * TEAM_F * 4;                 // 221184
    cudaFuncSetAttribute(mma_gemm_big,
                         cudaFuncAttributeMaxDynamicSharedMemorySize, SMEM_BIG);
    cudaFuncSetAttribute(loop_kernel,
                         cudaFuncAttributeMaxDynamicSharedMemorySize, SMEM_LOOP);

    prep_all<<<2048, 256>>>(feats, emb, Wf, Wh, W_ih0, W_hh0, W_ih1, W_hh1,
                            b_ih0, b_hh0, b_ih1, b_hh1);

    mma_gemm_fproj<<<dim3(196, 8), 256, SMEM_BF>>>(
        (const __nv_bfloat16*)p_featsb, (const __nv_bfloat16*)p_wfTb,
        (__nv_bfloat16*)p_fprojb, b_att);

    loop_kernel<<<NBLK, 512, SMEM_LOOP>>>(v);

    mma_gemm_big<<<dim3(32, 32), 256, SMEM_BIG>>>(
        (const float*)p_h0all, 1024, (const float*)p_w1c, 1024,
        (float*)p_gates1, 4096, (const float*)p_b1c, 1024);

    cell1_kernel<<<16384, 256>>>(out);
}